// round 4
// baseline (speedup 1.0000x reference)
#include <cuda_runtime.h>
#include <cstdint>

#define NTOK 98
#define CDIM 192
#define NH   6
#define HD   32
#define NWIN 64
#define BTOT 4096
#define ROWS (BTOT*NTOK)          // 401408
#define QKVN (3*CDIM)             // 576
#define PER_TENSOR (BTOT*NH*NTOK*HD)   // 77,070,336

// ---- scratch ----
__device__ float g_q[PER_TENSOR];
__device__ float g_k[PER_TENSOR];
__device__ float g_v[PER_TENSOR];
__device__ float g_o[ROWS*CDIM];           // attention output, (b, n, C) layout
__device__ float g_bias[NH*NTOK*NTOK];     // gathered relative-position bias

// ============================================================
// Kernel 1: gather relative position bias
// ============================================================
__global__ void bias_gather(const float* __restrict__ table, const int* __restrict__ rel) {
    int idx = blockIdx.x * blockDim.x + threadIdx.x;
    if (idx < NH * NTOK * NTOK) {
        int h  = idx / (NTOK * NTOK);
        int ij = idx - h * (NTOK * NTOK);
        g_bias[idx] = table[rel[ij] * NH + h];
    }
}

// ============================================================
// Kernel 2: QKV GEMM. 256x64 tile, K-chunk 8 double-buffered, 256 thr, 8x8/thread.
// ============================================================
__global__ __launch_bounds__(256, 2)
void qkv_gemm(const float* __restrict__ A, const float* __restrict__ W,
              const float* __restrict__ bvec) {
    __shared__ float As[2][8][256];
    __shared__ float Bs[2][8][64];

    const int tid = threadIdx.x;
    const int bM  = blockIdx.x * 256;
    const int bN  = blockIdx.y * 64;

    const int tx = tid & 7;       // N, x8
    const int ty = tid >> 3;      // M, x8 (0..31)

    const float* Ap = A + (size_t)(bM + tid) * CDIM;
    const bool  bload = tid < 128;
    const int   bn = tid & 63;
    const int   kh = (tid >> 6) & 1;      // which half of the k-chunk
    const float* Wp = W + (size_t)(bN + bn) * CDIM + kh * 4;

    float4 a0 = *(const float4*)(Ap + 0);
    float4 a1 = *(const float4*)(Ap + 4);
    float4 bf;
    if (bload) bf = *(const float4*)(Wp + 0);

    As[0][0][tid] = a0.x; As[0][1][tid] = a0.y; As[0][2][tid] = a0.z; As[0][3][tid] = a0.w;
    As[0][4][tid] = a1.x; As[0][5][tid] = a1.y; As[0][6][tid] = a1.z; As[0][7][tid] = a1.w;
    if (bload) {
        Bs[0][kh*4+0][bn] = bf.x; Bs[0][kh*4+1][bn] = bf.y;
        Bs[0][kh*4+2][bn] = bf.z; Bs[0][kh*4+3][bn] = bf.w;
    }
    __syncthreads();

    float acc[8][8];
#pragma unroll
    for (int i = 0; i < 8; i++)
#pragma unroll
        for (int j = 0; j < 8; j++) acc[i][j] = 0.f;

    for (int c = 0; c < 24; c++) {
        const int cur = c & 1;
        if (c < 23) {
            a0 = *(const float4*)(Ap + (c + 1) * 8);
            a1 = *(const float4*)(Ap + (c + 1) * 8 + 4);
            if (bload) bf = *(const float4*)(Wp + (c + 1) * 8);
        }
#pragma unroll
        for (int kk = 0; kk < 8; kk++) {
            float4 x0 = *(const float4*)&As[cur][kk][ty * 8];
            float4 x1 = *(const float4*)&As[cur][kk][ty * 8 + 4];
            float4 y0 = *(const float4*)&Bs[cur][kk][tx * 8];
            float4 y1 = *(const float4*)&Bs[cur][kk][tx * 8 + 4];
            float av[8] = {x0.x, x0.y, x0.z, x0.w, x1.x, x1.y, x1.z, x1.w};
            float bv[8] = {y0.x, y0.y, y0.z, y0.w, y1.x, y1.y, y1.z, y1.w};
#pragma unroll
            for (int i = 0; i < 8; i++)
#pragma unroll
                for (int j = 0; j < 8; j++)
                    acc[i][j] += av[i] * bv[j];
        }
        if (c < 23) {
            const int nb = cur ^ 1;
            As[nb][0][tid] = a0.x; As[nb][1][tid] = a0.y; As[nb][2][tid] = a0.z; As[nb][3][tid] = a0.w;
            As[nb][4][tid] = a1.x; As[nb][5][tid] = a1.y; As[nb][6][tid] = a1.z; As[nb][7][tid] = a1.w;
            if (bload) {
                Bs[nb][kh*4+0][bn] = bf.x; Bs[nb][kh*4+1][bn] = bf.y;
                Bs[nb][kh*4+2][bn] = bf.z; Bs[nb][kh*4+3][bn] = bf.w;
            }
        }
        __syncthreads();
    }

    // epilogue: scatter to q/k/v (b,h,n,d); whole 8-wide j-span stays in one head
    const int t       = bN / CDIM;                 // 0=q, 1=k, 2=v (64 | 192 boundaries)
    const int remBase = bN - t * CDIM + tx * 8;
    const int hh      = remBase >> 5;
    const int d0      = remBase & 31;
    float* tgt = (t == 0) ? g_q : (t == 1) ? g_k : g_v;
    const float sc = (t == 0) ? 0.17677669529663687f : 1.0f;

    const float4 bv0 = *(const float4*)&bvec[bN + tx * 8];
    const float4 bv1 = *(const float4*)&bvec[bN + tx * 8 + 4];
    const float bb[8] = {bv0.x, bv0.y, bv0.z, bv0.w, bv1.x, bv1.y, bv1.z, bv1.w};

#pragma unroll
    for (int i = 0; i < 8; i++) {
        int row = bM + ty * 8 + i;
        int b   = row / NTOK;
        int n   = row - b * NTOK;
        size_t base = (((size_t)b * NH + hh) * NTOK + n) * HD + d0;
        float4 o0, o1;
        o0.x = (acc[i][0] + bb[0]) * sc; o0.y = (acc[i][1] + bb[1]) * sc;
        o0.z = (acc[i][2] + bb[2]) * sc; o0.w = (acc[i][3] + bb[3]) * sc;
        o1.x = (acc[i][4] + bb[4]) * sc; o1.y = (acc[i][5] + bb[5]) * sc;
        o1.z = (acc[i][6] + bb[6]) * sc; o1.w = (acc[i][7] + bb[7]) * sc;
        *(float4*)&tgt[base]     = o0;
        *(float4*)&tgt[base + 4] = o1;
    }
}

// ============================================================
// Kernel 3: attention. One CTA per (b,h), 256 threads (8 warps).
// Each warp processes row-groups of 4: QK with 4-row reuse of K loads,
// transposed probs in smem, PV with float4 broadcast of 4 rows' probs.
// ============================================================
__global__ __launch_bounds__(256)
void attn_kernel(const float* __restrict__ mask) {
    __shared__ float Ks[NTOK * 36];
    __shared__ float Vs[NTOK * 36];
    __shared__ float q4[8][4][32];
    __shared__ float pT[8][NTOK][4];

    const int bh = blockIdx.x;
    const int b  = bh / NH;
    const int h  = bh - b * NH;
    const int w  = b & (NWIN - 1);

    const float* Kp = g_k + (size_t)bh * NTOK * HD;
    const float* Vp = g_v + (size_t)bh * NTOK * HD;
    const float* Qp = g_q + (size_t)bh * NTOK * HD;

    const int tid = threadIdx.x;
    for (int idx = tid; idx < NTOK * HD; idx += 256) {
        int j = idx >> 5, d = idx & 31;
        Ks[j * 36 + d] = Kp[idx];
        Vs[j * 36 + d] = Vp[idx];
    }
    __syncthreads();

    const int warp = tid >> 5, lane = tid & 31;
    const float* biasH = g_bias + (size_t)h * NTOK * NTOK;
    const float* maskW = mask   + (size_t)w * NTOK * NTOK;

    // 25 groups of 4 rows (last group: rows 96,97 valid; 98,99 clamped/discarded)
    for (int g = warp; g < 25; g += 8) {
        const int i0 = g * 4;

        // stage q rows for the group (broadcast-readable)
#pragma unroll
        for (int r = 0; r < 4; r++) {
            int i = min(i0 + r, NTOK - 1);
            q4[warp][r][lane] = Qp[i * HD + lane];
        }
        __syncwarp();

        float s[4][4];
#pragma unroll
        for (int t = 0; t < 4; t++) {
            const int j  = lane + t * 32;
            const int jc = min(j, NTOK - 1);
            float a0 = 0.f, a1 = 0.f, a2 = 0.f, a3 = 0.f;
#pragma unroll
            for (int d4 = 0; d4 < 8; d4++) {
                float4 kv = *(const float4*)&Ks[jc * 36 + d4 * 4];
                float4 r0 = *(const float4*)&q4[warp][0][d4 * 4];
                float4 r1 = *(const float4*)&q4[warp][1][d4 * 4];
                float4 r2 = *(const float4*)&q4[warp][2][d4 * 4];
                float4 r3 = *(const float4*)&q4[warp][3][d4 * 4];
                a0 += kv.x*r0.x + kv.y*r0.y + kv.z*r0.z + kv.w*r0.w;
                a1 += kv.x*r1.x + kv.y*r1.y + kv.z*r1.z + kv.w*r1.w;
                a2 += kv.x*r2.x + kv.y*r2.y + kv.z*r2.z + kv.w*r2.w;
                a3 += kv.x*r3.x + kv.y*r3.y + kv.z*r3.z + kv.w*r3.w;
            }
            if (j < NTOK) {
#pragma unroll
                for (int r = 0; r < 4; r++) {
                    int i = min(i0 + r, NTOK - 1);
                    float add = biasH[i * NTOK + j] + maskW[i * NTOK + j];
                    s[r][t] = ((r == 0) ? a0 : (r == 1) ? a1 : (r == 2) ? a2 : a3) + add;
                }
            } else {
                s[0][t] = -1e30f; s[1][t] = -1e30f; s[2][t] = -1e30f; s[3][t] = -1e30f;
            }
        }

        // per-row softmax
#pragma unroll
        for (int r = 0; r < 4; r++) {
            float m = fmaxf(fmaxf(s[r][0], s[r][1]), fmaxf(s[r][2], s[r][3]));
#pragma unroll
            for (int off = 16; off; off >>= 1)
                m = fmaxf(m, __shfl_xor_sync(0xffffffffu, m, off));
            float sum = 0.f;
#pragma unroll
            for (int t = 0; t < 4; t++) {
                s[r][t] = __expf(s[r][t] - m);
                sum += s[r][t];
            }
#pragma unroll
            for (int off = 16; off; off >>= 1)
                sum += __shfl_xor_sync(0xffffffffu, sum, off);
            float iv = 1.0f / sum;
#pragma unroll
            for (int t = 0; t < 4; t++) s[r][t] *= iv;
        }

        // store probs transposed: pT[j][r], one STS.128 per t
#pragma unroll
        for (int t = 0; t < 4; t++) {
            int j = lane + t * 32;
            if (j < NTOK)
                *(float4*)&pT[warp][j][0] = make_float4(s[0][t], s[1][t], s[2][t], s[3][t]);
        }
        __syncwarp();

        // PV: lane = d; 1 scalar LDS + 1 broadcast LDS.128 per 4 FFMA
        float o0 = 0.f, o1 = 0.f, o2 = 0.f, o3 = 0.f;
#pragma unroll 2
        for (int j = 0; j < NTOK; j++) {
            float  v = Vs[j * 36 + lane];
            float4 p = *(const float4*)&pT[warp][j][0];
            o0 += p.x * v; o1 += p.y * v; o2 += p.z * v; o3 += p.w * v;
        }

#pragma unroll
        for (int r = 0; r < 4; r++) {
            int i = i0 + r;
            if (i < NTOK) {
                float ov = (r == 0) ? o0 : (r == 1) ? o1 : (r == 2) ? o2 : o3;
                g_o[((size_t)(b * NTOK + i)) * CDIM + h * HD + lane] = ov;
            }
        }
        __syncwarp();   // protect q4/pT before next group
    }
}

// ============================================================
// Kernel 4: projection GEMM, same 256x64 structure.
// ============================================================
__global__ __launch_bounds__(256, 2)
void proj_gemm(const float* __restrict__ W, const float* __restrict__ bvec,
               float* __restrict__ C) {
    __shared__ float As[2][8][256];
    __shared__ float Bs[2][8][64];

    const int tid = threadIdx.x;
    const int bM  = blockIdx.x * 256;
    const int bN  = blockIdx.y * 64;

    const int tx = tid & 7;
    const int ty = tid >> 3;

    const float* Ap = g_o + (size_t)(bM + tid) * CDIM;
    const bool  bload = tid < 128;
    const int   bn = tid & 63;
    const int   kh = (tid >> 6) & 1;
    const float* Wp = W + (size_t)(bN + bn) * CDIM + kh * 4;

    float4 a0 = *(const float4*)(Ap + 0);
    float4 a1 = *(const float4*)(Ap + 4);
    float4 bf;
    if (bload) bf = *(const float4*)(Wp + 0);

    As[0][0][tid] = a0.x; As[0][1][tid] = a0.y; As[0][2][tid] = a0.z; As[0][3][tid] = a0.w;
    As[0][4][tid] = a1.x; As[0][5][tid] = a1.y; As[0][6][tid] = a1.z; As[0][7][tid] = a1.w;
    if (bload) {
        Bs[0][kh*4+0][bn] = bf.x; Bs[0][kh*4+1][bn] = bf.y;
        Bs[0][kh*4+2][bn] = bf.z; Bs[0][kh*4+3][bn] = bf.w;
    }
    __syncthreads();

    float acc[8][8];
#pragma unroll
    for (int i = 0; i < 8; i++)
#pragma unroll
        for (int j = 0; j < 8; j++) acc[i][j] = 0.f;

    for (int c = 0; c < 24; c++) {
        const int cur = c & 1;
        if (c < 23) {
            a0 = *(const float4*)(Ap + (c + 1) * 8);
            a1 = *(const float4*)(Ap + (c + 1) * 8 + 4);
            if (bload) bf = *(const float4*)(Wp + (c + 1) * 8);
        }
#pragma unroll
        for (int kk = 0; kk < 8; kk++) {
            float4 x0 = *(const float4*)&As[cur][kk][ty * 8];
            float4 x1 = *(const float4*)&As[cur][kk][ty * 8 + 4];
            float4 y0 = *(const float4*)&Bs[cur][kk][tx * 8];
            float4 y1 = *(const float4*)&Bs[cur][kk][tx * 8 + 4];
            float av[8] = {x0.x, x0.y, x0.z, x0.w, x1.x, x1.y, x1.z, x1.w};
            float bv[8] = {y0.x, y0.y, y0.z, y0.w, y1.x, y1.y, y1.z, y1.w};
#pragma unroll
            for (int i = 0; i < 8; i++)
#pragma unroll
                for (int j = 0; j < 8; j++)
                    acc[i][j] += av[i] * bv[j];
        }
        if (c < 23) {
            const int nb = cur ^ 1;
            As[nb][0][tid] = a0.x; As[nb][1][tid] = a0.y; As[nb][2][tid] = a0.z; As[nb][3][tid] = a0.w;
            As[nb][4][tid] = a1.x; As[nb][5][tid] = a1.y; As[nb][6][tid] = a1.z; As[nb][7][tid] = a1.w;
            if (bload) {
                Bs[nb][kh*4+0][bn] = bf.x; Bs[nb][kh*4+1][bn] = bf.y;
                Bs[nb][kh*4+2][bn] = bf.z; Bs[nb][kh*4+3][bn] = bf.w;
            }
        }
        __syncthreads();
    }

    const float4 bv0 = *(const float4*)&bvec[bN + tx * 8];
    const float4 bv1 = *(const float4*)&bvec[bN + tx * 8 + 4];
#pragma unroll
    for (int i = 0; i < 8; i++) {
        int row = bM + ty * 8 + i;
        float4 o0, o1;
        o0.x = acc[i][0] + bv0.x; o0.y = acc[i][1] + bv0.y;
        o0.z = acc[i][2] + bv0.z; o0.w = acc[i][3] + bv0.w;
        o1.x = acc[i][4] + bv1.x; o1.y = acc[i][5] + bv1.y;
        o1.z = acc[i][6] + bv1.z; o1.w = acc[i][7] + bv1.w;
        *(float4*)&C[(size_t)row * CDIM + bN + tx * 8]     = o0;
        *(float4*)&C[(size_t)row * CDIM + bN + tx * 8 + 4] = o1;
    }
}

// ============================================================
extern "C" void kernel_launch(void* const* d_in, const int* in_sizes, int n_in,
                              void* d_out, int out_size) {
    const float* x      = (const float*)d_in[0];
    const float* mask   = (const float*)d_in[1];
    const float* qkv_w  = (const float*)d_in[2];
    const float* qkv_b  = (const float*)d_in[3];
    const float* proj_w = (const float*)d_in[4];
    const float* proj_b = (const float*)d_in[5];
    const float* rpb    = (const float*)d_in[6];
    const int*   rel    = (const int*)d_in[7];
    float* out = (float*)d_out;

    bias_gather<<<(NH * NTOK * NTOK + 255) / 256, 256>>>(rpb, rel);

    dim3 g1(ROWS / 256, QKVN / 64);     // 1568 x 9
    qkv_gemm<<<g1, 256>>>(x, qkv_w, qkv_b);

    attn_kernel<<<BTOT * NH, 256>>>(mask);

    dim3 g2(ROWS / 256, CDIM / 64);     // 1568 x 3
    proj_gemm<<<g2, 256>>>(proj_w, proj_b, out);
}

// round 5
// speedup vs baseline: 1.6252x; 1.6252x over previous
#include <cuda_runtime.h>
#include <cstdint>

#define NTOK 98
#define CDIM 192
#define NH   6
#define HD   32
#define NWIN 64
#define BTOT 4096
#define ROWS (BTOT*NTOK)          // 401408
#define QKVN (3*CDIM)             // 576
#define PER_TENSOR (BTOT*NH*NTOK*HD)   // 77,070,336

// ---- scratch ----
__device__ float g_q[PER_TENSOR];
__device__ float g_k[PER_TENSOR];
__device__ float g_v[PER_TENSOR];
__device__ float g_o[ROWS*CDIM];           // attention output, (b, n, C) layout
__device__ float g_bias[NH*NTOK*NTOK];     // gathered relative-position bias

// ============================================================
// Kernel 1: gather relative position bias
// ============================================================
__global__ void bias_gather(const float* __restrict__ table, const int* __restrict__ rel) {
    int idx = blockIdx.x * blockDim.x + threadIdx.x;
    if (idx < NH * NTOK * NTOK) {
        int h  = idx / (NTOK * NTOK);
        int ij = idx - h * (NTOK * NTOK);
        g_bias[idx] = table[rel[ij] * NH + h];
    }
}

// ============================================================
// Kernel 2: QKV GEMM. 128x64 tile, K-chunk 16, 256 threads, 8x4/thread
// (Round-2 proven shape, regs ~80) + register prefetch of next chunk.
// Epilogue scatters into g_q/g_k/g_v (b,h,n,d); q pre-scaled.
// ============================================================
__global__ __launch_bounds__(256)
void qkv_gemm(const float* __restrict__ A, const float* __restrict__ W,
              const float* __restrict__ bvec) {
    __shared__ float As[16 * 128];
    __shared__ float Bs[16 * 64];

    const int tid    = threadIdx.x;
    const int blockM = blockIdx.x * 128;
    const int blockN = blockIdx.y * 64;

    const int ar = tid >> 2;          // 0..63
    const int ac = (tid & 3) << 2;    // 0,4,8,12

    const float* Ag0 = A + (size_t)(blockM + ar)      * CDIM + ac;
    const float* Ag1 = A + (size_t)(blockM + ar + 64) * CDIM + ac;
    const float* Wg  = W + (size_t)(blockN + ar)      * CDIM + ac;

    const int tx = tid & 15;          // N dir (x4)
    const int ty = tid >> 4;          // M dir (x8)

    float acc[8][4];
#pragma unroll
    for (int i = 0; i < 8; i++)
#pragma unroll
        for (int j = 0; j < 4; j++) acc[i][j] = 0.f;

    float4 a0 = *(const float4*)(Ag0);
    float4 a1 = *(const float4*)(Ag1);
    float4 w0 = *(const float4*)(Wg);

    for (int c = 0; c < 12; c++) {
        As[(ac + 0) * 128 + ar] = a0.x;
        As[(ac + 1) * 128 + ar] = a0.y;
        As[(ac + 2) * 128 + ar] = a0.z;
        As[(ac + 3) * 128 + ar] = a0.w;
        As[(ac + 0) * 128 + ar + 64] = a1.x;
        As[(ac + 1) * 128 + ar + 64] = a1.y;
        As[(ac + 2) * 128 + ar + 64] = a1.z;
        As[(ac + 3) * 128 + ar + 64] = a1.w;
        Bs[(ac + 0) * 64 + ar] = w0.x;
        Bs[(ac + 1) * 64 + ar] = w0.y;
        Bs[(ac + 2) * 64 + ar] = w0.z;
        Bs[(ac + 3) * 64 + ar] = w0.w;
        __syncthreads();

        if (c < 11) {      // prefetch next chunk while this one computes
            a0 = *(const float4*)(Ag0 + (c + 1) * 16);
            a1 = *(const float4*)(Ag1 + (c + 1) * 16);
            w0 = *(const float4*)(Wg  + (c + 1) * 16);
        }

#pragma unroll
        for (int k = 0; k < 16; k++) {
            float4 av0 = *(const float4*)&As[k * 128 + ty * 8];
            float4 av1 = *(const float4*)&As[k * 128 + ty * 8 + 4];
            float4 bv  = *(const float4*)&Bs[k * 64  + tx * 4];
            float a[8] = {av0.x, av0.y, av0.z, av0.w, av1.x, av1.y, av1.z, av1.w};
            float b[4] = {bv.x, bv.y, bv.z, bv.w};
#pragma unroll
            for (int i = 0; i < 8; i++)
#pragma unroll
                for (int j = 0; j < 4; j++)
                    acc[i][j] += a[i] * b[j];
        }
        __syncthreads();
    }

    const float scale = 0.17677669529663687f;  // 32^-0.5
#pragma unroll
    for (int i = 0; i < 8; i++) {
        int row = blockM + ty * 8 + i;
        int b   = row / NTOK;
        int n   = row - b * NTOK;
#pragma unroll
        for (int j = 0; j < 4; j++) {
            int nn  = blockN + tx * 4 + j;
            float v = acc[i][j] + bvec[nn];
            int t   = nn / CDIM;
            int rem = nn - t * CDIM;
            int hh  = rem >> 5;
            int d   = rem & 31;
            size_t off = (((size_t)b * NH + hh) * NTOK + n) * HD + d;
            if (t == 0)      g_q[off] = v * scale;
            else if (t == 1) g_k[off] = v;
            else             g_v[off] = v;
        }
    }
}

// ============================================================
// Kernel 3: attention. One CTA per (b,h), 256 threads (8 warps).
// Each warp processes row-groups of 4: QK with 4-row reuse of K loads,
// transposed probs in smem, PV with float4 broadcast of 4 rows' probs.
// ============================================================
__global__ __launch_bounds__(256)
void attn_kernel(const float* __restrict__ mask) {
    __shared__ float Ks[NTOK * 36];
    __shared__ float Vs[NTOK * 36];
    __shared__ float q4[8][4][32];
    __shared__ float pT[8][NTOK][4];

    const int bh = blockIdx.x;
    const int b  = bh / NH;
    const int h  = bh - b * NH;
    const int w  = b & (NWIN - 1);

    const float* Kp = g_k + (size_t)bh * NTOK * HD;
    const float* Vp = g_v + (size_t)bh * NTOK * HD;
    const float* Qp = g_q + (size_t)bh * NTOK * HD;

    const int tid = threadIdx.x;
    for (int idx = tid; idx < NTOK * HD; idx += 256) {
        int j = idx >> 5, d = idx & 31;
        Ks[j * 36 + d] = Kp[idx];
        Vs[j * 36 + d] = Vp[idx];
    }
    __syncthreads();

    const int warp = tid >> 5, lane = tid & 31;
    const float* biasH = g_bias + (size_t)h * NTOK * NTOK;
    const float* maskW = mask   + (size_t)w * NTOK * NTOK;

    // 25 groups of 4 rows (rows 98,99 of last group clamped/discarded)
    for (int g = warp; g < 25; g += 8) {
        const int i0 = g * 4;

#pragma unroll
        for (int r = 0; r < 4; r++) {
            int i = min(i0 + r, NTOK - 1);
            q4[warp][r][lane] = Qp[i * HD + lane];
        }
        __syncwarp();

        float s[4][4];
#pragma unroll
        for (int t = 0; t < 4; t++) {
            const int j  = lane + t * 32;
            const int jc = min(j, NTOK - 1);
            float a0 = 0.f, a1 = 0.f, a2 = 0.f, a3 = 0.f;
#pragma unroll
            for (int d4 = 0; d4 < 8; d4++) {
                float4 kv = *(const float4*)&Ks[jc * 36 + d4 * 4];
                float4 r0 = *(const float4*)&q4[warp][0][d4 * 4];
                float4 r1 = *(const float4*)&q4[warp][1][d4 * 4];
                float4 r2 = *(const float4*)&q4[warp][2][d4 * 4];
                float4 r3 = *(const float4*)&q4[warp][3][d4 * 4];
                a0 += kv.x*r0.x + kv.y*r0.y + kv.z*r0.z + kv.w*r0.w;
                a1 += kv.x*r1.x + kv.y*r1.y + kv.z*r1.z + kv.w*r1.w;
                a2 += kv.x*r2.x + kv.y*r2.y + kv.z*r2.z + kv.w*r2.w;
                a3 += kv.x*r3.x + kv.y*r3.y + kv.z*r3.z + kv.w*r3.w;
            }
            if (j < NTOK) {
#pragma unroll
                for (int r = 0; r < 4; r++) {
                    int i = min(i0 + r, NTOK - 1);
                    float add = biasH[i * NTOK + j] + maskW[i * NTOK + j];
                    s[r][t] = ((r == 0) ? a0 : (r == 1) ? a1 : (r == 2) ? a2 : a3) + add;
                }
            } else {
                s[0][t] = -1e30f; s[1][t] = -1e30f; s[2][t] = -1e30f; s[3][t] = -1e30f;
            }
        }

        // per-row softmax
#pragma unroll
        for (int r = 0; r < 4; r++) {
            float m = fmaxf(fmaxf(s[r][0], s[r][1]), fmaxf(s[r][2], s[r][3]));
#pragma unroll
            for (int off = 16; off; off >>= 1)
                m = fmaxf(m, __shfl_xor_sync(0xffffffffu, m, off));
            float sum = 0.f;
#pragma unroll
            for (int t = 0; t < 4; t++) {
                s[r][t] = __expf(s[r][t] - m);
                sum += s[r][t];
            }
#pragma unroll
            for (int off = 16; off; off >>= 1)
                sum += __shfl_xor_sync(0xffffffffu, sum, off);
            float iv = 1.0f / sum;
#pragma unroll
            for (int t = 0; t < 4; t++) s[r][t] *= iv;
        }

        // store probs transposed: pT[j][r] (one STS.128 per t)
#pragma unroll
        for (int t = 0; t < 4; t++) {
            int j = lane + t * 32;
            if (j < NTOK)
                *(float4*)&pT[warp][j][0] = make_float4(s[0][t], s[1][t], s[2][t], s[3][t]);
        }
        __syncwarp();

        // PV: lane = d; 1 scalar LDS + 1 broadcast LDS.128 per 4 FFMA
        float o0 = 0.f, o1 = 0.f, o2 = 0.f, o3 = 0.f;
#pragma unroll 2
        for (int j = 0; j < NTOK; j++) {
            float  v = Vs[j * 36 + lane];
            float4 p = *(const float4*)&pT[warp][j][0];
            o0 += p.x * v; o1 += p.y * v; o2 += p.z * v; o3 += p.w * v;
        }

#pragma unroll
        for (int r = 0; r < 4; r++) {
            int i = i0 + r;
            if (i < NTOK) {
                float ov = (r == 0) ? o0 : (r == 1) ? o1 : (r == 2) ? o2 : o3;
                g_o[((size_t)(b * NTOK + i)) * CDIM + h * HD + lane] = ov;
            }
        }
        __syncwarp();   // protect q4/pT before next group
    }
}

// ============================================================
// Kernel 4: projection GEMM. Same 128x64 / 8x4 shape + prefetch.
// ============================================================
__global__ __launch_bounds__(256)
void proj_gemm(const float* __restrict__ W, const float* __restrict__ bvec,
               float* __restrict__ C) {
    __shared__ float As[16 * 128];
    __shared__ float Bs[16 * 64];

    const int tid    = threadIdx.x;
    const int blockM = blockIdx.x * 128;
    const int blockN = blockIdx.y * 64;

    const int ar = tid >> 2;
    const int ac = (tid & 3) << 2;

    const float* Ag0 = g_o + (size_t)(blockM + ar)      * CDIM + ac;
    const float* Ag1 = g_o + (size_t)(blockM + ar + 64) * CDIM + ac;
    const float* Wg  = W   + (size_t)(blockN + ar)      * CDIM + ac;

    const int tx = tid & 15;
    const int ty = tid >> 4;

    float acc[8][4];
#pragma unroll
    for (int i = 0; i < 8; i++)
#pragma unroll
        for (int j = 0; j < 4; j++) acc[i][j] = 0.f;

    float4 a0 = *(const float4*)(Ag0);
    float4 a1 = *(const float4*)(Ag1);
    float4 w0 = *(const float4*)(Wg);

    for (int c = 0; c < 12; c++) {
        As[(ac + 0) * 128 + ar] = a0.x;
        As[(ac + 1) * 128 + ar] = a0.y;
        As[(ac + 2) * 128 + ar] = a0.z;
        As[(ac + 3) * 128 + ar] = a0.w;
        As[(ac + 0) * 128 + ar + 64] = a1.x;
        As[(ac + 1) * 128 + ar + 64] = a1.y;
        As[(ac + 2) * 128 + ar + 64] = a1.z;
        As[(ac + 3) * 128 + ar + 64] = a1.w;
        Bs[(ac + 0) * 64 + ar] = w0.x;
        Bs[(ac + 1) * 64 + ar] = w0.y;
        Bs[(ac + 2) * 64 + ar] = w0.z;
        Bs[(ac + 3) * 64 + ar] = w0.w;
        __syncthreads();

        if (c < 11) {
            a0 = *(const float4*)(Ag0 + (c + 1) * 16);
            a1 = *(const float4*)(Ag1 + (c + 1) * 16);
            w0 = *(const float4*)(Wg  + (c + 1) * 16);
        }

#pragma unroll
        for (int k = 0; k < 16; k++) {
            float4 av0 = *(const float4*)&As[k * 128 + ty * 8];
            float4 av1 = *(const float4*)&As[k * 128 + ty * 8 + 4];
            float4 bv  = *(const float4*)&Bs[k * 64  + tx * 4];
            float a[8] = {av0.x, av0.y, av0.z, av0.w, av1.x, av1.y, av1.z, av1.w};
            float b[4] = {bv.x, bv.y, bv.z, bv.w};
#pragma unroll
            for (int i = 0; i < 8; i++)
#pragma unroll
                for (int j = 0; j < 4; j++)
                    acc[i][j] += a[i] * b[j];
        }
        __syncthreads();
    }

#pragma unroll
    for (int i = 0; i < 8; i++) {
        int row = blockM + ty * 8 + i;
        int nn0 = blockN + tx * 4;
        float4 o;
        o.x = acc[i][0] + bvec[nn0 + 0];
        o.y = acc[i][1] + bvec[nn0 + 1];
        o.z = acc[i][2] + bvec[nn0 + 2];
        o.w = acc[i][3] + bvec[nn0 + 3];
        *(float4*)&C[(size_t)row * CDIM + nn0] = o;
    }
}

// ============================================================
extern "C" void kernel_launch(void* const* d_in, const int* in_sizes, int n_in,
                              void* d_out, int out_size) {
    const float* x      = (const float*)d_in[0];
    const float* mask   = (const float*)d_in[1];
    const float* qkv_w  = (const float*)d_in[2];
    const float* qkv_b  = (const float*)d_in[3];
    const float* proj_w = (const float*)d_in[4];
    const float* proj_b = (const float*)d_in[5];
    const float* rpb    = (const float*)d_in[6];
    const int*   rel    = (const int*)d_in[7];
    float* out = (float*)d_out;

    bias_gather<<<(NH * NTOK * NTOK + 255) / 256, 256>>>(rpb, rel);

    dim3 g1(ROWS / 128, QKVN / 64);     // 3136 x 9
    qkv_gemm<<<g1, 256>>>(x, qkv_w, qkv_b);

    attn_kernel<<<BTOT * NH, 256>>>(mask);

    dim3 g2(ROWS / 128, CDIM / 64);     // 3136 x 3
    proj_gemm<<<g2, 256>>>(proj_w, proj_b, out);
}

// round 6
// speedup vs baseline: 2.1145x; 1.3011x over previous
#include <cuda_runtime.h>
#include <cstdint>

#define NTOK 98
#define CDIM 192
#define NH   6
#define HD   32
#define NWIN 64
#define BTOT 4096
#define ROWS (BTOT*NTOK)          // 401408
#define QKVN (3*CDIM)             // 576
#define PER_TENSOR (BTOT*NH*NTOK*HD)   // 77,070,336

// ---- scratch ----
__device__ float g_q[PER_TENSOR];
__device__ float g_k[PER_TENSOR];
__device__ float g_v[PER_TENSOR];
__device__ float g_o[ROWS*CDIM];           // attention output, (b, n, C) layout
__device__ float g_bias[NH*NTOK*NTOK];     // gathered relative-position bias

// ---- tf32 helpers ----
__device__ __forceinline__ uint32_t f2tf(float x) {
    uint32_t r; asm("cvt.rna.tf32.f32 %0, %1;" : "=r"(r) : "f"(x)); return r;
}
// 3xTF32 split: big = rn_tf32(x), small = rn_tf32(x - big)
__device__ __forceinline__ void tf32_split(float x, uint32_t& big, uint32_t& small) {
    big = f2tf(x);
    small = f2tf(x - __uint_as_float(big));
}

#define MMA_TF32(d, a, b)                                                     \
    asm volatile(                                                             \
        "mma.sync.aligned.m16n8k8.row.col.f32.tf32.tf32.f32 "                 \
        "{%0,%1,%2,%3}, {%4,%5,%6,%7}, {%8,%9}, {%0,%1,%2,%3};"               \
        : "+f"(d[0]), "+f"(d[1]), "+f"(d[2]), "+f"(d[3])                      \
        : "r"(a[0]), "r"(a[1]), "r"(a[2]), "r"(a[3]), "r"(b[0]), "r"(b[1]))

// ============================================================
// Kernel 1: gather relative position bias
// ============================================================
__global__ void bias_gather(const float* __restrict__ table, const int* __restrict__ rel) {
    int idx = blockIdx.x * blockDim.x + threadIdx.x;
    if (idx < NH * NTOK * NTOK) {
        int h  = idx / (NTOK * NTOK);
        int ij = idx - h * (NTOK * NTOK);
        g_bias[idx] = table[rel[ij] * NH + h];
    }
}

// ============================================================
// Kernel 2: QKV GEMM via 3xTF32 mma.m16n8k8.
// CTA tile 128M x 64N, 8 warps (4Mx2N), warp tile 32x32 (2 m16 x 4 n8).
// K-chunk 16, register-prefetched. Smem pitch 20 -> conflict-free frags.
// Epilogue scatters into g_q/g_k/g_v (b,h,n,d); q pre-scaled.
// ============================================================
#define PITCH 20

__global__ __launch_bounds__(256)
void qkv_gemm(const float* __restrict__ A, const float* __restrict__ W,
              const float* __restrict__ bvec) {
    __shared__ float As[128 * PITCH];
    __shared__ float Bs[64 * PITCH];

    const int tid  = threadIdx.x;
    const int bM   = blockIdx.x * 128;
    const int bN   = blockIdx.y * 64;
    const int lane = tid & 31;
    const int wid  = tid >> 5;
    const int wm   = wid & 3;        // 4 warps in M (x32)
    const int wn   = wid >> 2;       // 2 warps in N (x32)

    // global load assignment
    const int arow = tid >> 1;                  // 0..127
    const int acol = (tid & 1) * 8;             // 0 or 8
    const int brow = tid & 63;                  // 0..63
    const int bcol = (tid >> 6) * 4;            // 0,4,8,12
    const float* Ag = A + (size_t)(bM + arow) * CDIM + acol;
    const float* Wg = W + (size_t)(bN + brow) * CDIM + bcol;

    float acc[2][4][4];
#pragma unroll
    for (int mt = 0; mt < 2; mt++)
#pragma unroll
        for (int nt = 0; nt < 4; nt++)
#pragma unroll
            for (int q = 0; q < 4; q++) acc[mt][nt][q] = 0.f;

    float4 pa0 = *(const float4*)(Ag);
    float4 pa1 = *(const float4*)(Ag + 4);
    float4 pb  = *(const float4*)(Wg);

    const int g4 = lane >> 2;   // groupID
    const int t4 = lane & 3;    // thread-in-group

    for (int c = 0; c < 12; c++) {
        *(float4*)&As[arow * PITCH + acol]     = pa0;
        *(float4*)&As[arow * PITCH + acol + 4] = pa1;
        *(float4*)&Bs[brow * PITCH + bcol]     = pb;
        __syncthreads();

        if (c < 11) {
            pa0 = *(const float4*)(Ag + (c + 1) * 16);
            pa1 = *(const float4*)(Ag + (c + 1) * 16 + 4);
            pb  = *(const float4*)(Wg + (c + 1) * 16);
        }

#pragma unroll
        for (int ks = 0; ks < 16; ks += 8) {
            uint32_t Ab[2][4], Asm[2][4];
#pragma unroll
            for (int mt = 0; mt < 2; mt++) {
                const int r = wm * 32 + mt * 16 + g4;
#pragma unroll
                for (int q = 0; q < 4; q++) {
                    int rr = r + (q & 1) * 8;
                    int cc = ks + t4 + (q >> 1) * 4;
                    tf32_split(As[rr * PITCH + cc], Ab[mt][q], Asm[mt][q]);
                }
            }
            uint32_t Bb[4][2], Bsm[4][2];
#pragma unroll
            for (int nt = 0; nt < 4; nt++) {
                const int nb = wn * 32 + nt * 8 + g4;
#pragma unroll
                for (int q = 0; q < 2; q++) {
                    int cc = ks + t4 + q * 4;
                    tf32_split(Bs[nb * PITCH + cc], Bb[nt][q], Bsm[nt][q]);
                }
            }
#pragma unroll
            for (int mt = 0; mt < 2; mt++)
#pragma unroll
                for (int nt = 0; nt < 4; nt++) {
                    MMA_TF32(acc[mt][nt], Ab[mt], Bb[nt]);
                    MMA_TF32(acc[mt][nt], Ab[mt], Bsm[nt]);
                    MMA_TF32(acc[mt][nt], Asm[mt], Bb[nt]);
                }
        }
        __syncthreads();
    }

    // epilogue: scatter into q/k/v (b,h,n,d)
    const float scale = 0.17677669529663687f;
#pragma unroll
    for (int mt = 0; mt < 2; mt++) {
        int r0 = bM + wm * 32 + mt * 16 + g4;
        int r1 = r0 + 8;
        int b0 = r0 / NTOK, n0 = r0 - b0 * NTOK;
        int b1 = r1 / NTOK, n1 = r1 - b1 * NTOK;
#pragma unroll
        for (int nt = 0; nt < 4; nt++) {
            int c0  = bN + wn * 32 + nt * 8 + t4 * 2;
            int t   = c0 / CDIM;
            int rem = c0 - t * CDIM;
            int hh  = rem >> 5;
            int d   = rem & 31;
            float* tgt = (t == 0) ? g_q : (t == 1) ? g_k : g_v;
            float sc   = (t == 0) ? scale : 1.0f;
            float bb0 = bvec[c0], bb1 = bvec[c0 + 1];
            float2 v0, v1;
            v0.x = (acc[mt][nt][0] + bb0) * sc;
            v0.y = (acc[mt][nt][1] + bb1) * sc;
            v1.x = (acc[mt][nt][2] + bb0) * sc;
            v1.y = (acc[mt][nt][3] + bb1) * sc;
            size_t o0 = (((size_t)b0 * NH + hh) * NTOK + n0) * HD + d;
            size_t o1 = (((size_t)b1 * NH + hh) * NTOK + n1) * HD + d;
            *(float2*)&tgt[o0] = v0;
            *(float2*)&tgt[o1] = v1;
        }
    }
}

// ============================================================
// Kernel 3: attention (proven R2 version). One CTA per (b,h), 4 warps.
// ============================================================
__global__ __launch_bounds__(128)
void attn_kernel(const float* __restrict__ mask) {
    __shared__ float Ks[NTOK * 36];
    __shared__ float Vs[NTOK * 36];
    __shared__ float probs[4][NTOK + 2];
    __shared__ float qrow[4][32];

    const int bh = blockIdx.x;
    const int b  = bh / NH;
    const int h  = bh - b * NH;
    const int w  = b & (NWIN - 1);

    const float* Kp = g_k + (size_t)bh * NTOK * HD;
    const float* Vp = g_v + (size_t)bh * NTOK * HD;
    const float* Qp = g_q + (size_t)bh * NTOK * HD;

    const int tid = threadIdx.x;
    for (int idx = tid; idx < NTOK * HD; idx += 128) {
        int j = idx >> 5, d = idx & 31;
        Ks[j * 36 + d] = Kp[idx];
        Vs[j * 36 + d] = Vp[idx];
    }
    __syncthreads();

    const int warp = tid >> 5, lane = tid & 31;
    const float* biasH = g_bias + (size_t)h * NTOK * NTOK;
    const float* maskW = mask   + (size_t)w * NTOK * NTOK;

    for (int i = warp; i < NTOK; i += 4) {
        qrow[warp][lane] = Qp[i * HD + lane];
        __syncwarp();

        const float* bm = biasH + i * NTOK;
        const float* mk = maskW + i * NTOK;

        float s[4];
#pragma unroll
        for (int t = 0; t < 4; t++) {
            int j = lane + t * 32;
            if (j < NTOK) {
                float acc = 0.f;
#pragma unroll
                for (int d4 = 0; d4 < 8; d4++) {
                    float4 kv = *(const float4*)&Ks[j * 36 + d4 * 4];
                    float4 qv = *(const float4*)&qrow[warp][d4 * 4];
                    acc += kv.x * qv.x + kv.y * qv.y + kv.z * qv.z + kv.w * qv.w;
                }
                s[t] = acc + bm[j] + mk[j];
            } else {
                s[t] = -1e30f;
            }
        }

        float m = fmaxf(fmaxf(s[0], s[1]), fmaxf(s[2], s[3]));
#pragma unroll
        for (int off = 16; off; off >>= 1)
            m = fmaxf(m, __shfl_xor_sync(0xffffffffu, m, off));

        float sum = 0.f;
#pragma unroll
        for (int t = 0; t < 4; t++) {
            int j = lane + t * 32;
            s[t] = (j < NTOK) ? __expf(s[t] - m) : 0.f;
            sum += s[t];
        }
#pragma unroll
        for (int off = 16; off; off >>= 1)
            sum += __shfl_xor_sync(0xffffffffu, sum, off);

        float inv = 1.0f / sum;
#pragma unroll
        for (int t = 0; t < 4; t++) {
            int j = lane + t * 32;
            if (j < NTOK) probs[warp][j] = s[t] * inv;
        }
        __syncwarp();

        float o = 0.f;
#pragma unroll 2
        for (int j = 0; j < NTOK; j++)
            o += probs[warp][j] * Vs[j * 36 + lane];

        g_o[((size_t)(b * NTOK + i)) * CDIM + h * HD + lane] = o;
        __syncwarp();
    }
}

// ============================================================
// Kernel 4: projection GEMM via 3xTF32 mma. Same tiling as qkv.
// ============================================================
__global__ __launch_bounds__(256)
void proj_gemm(const float* __restrict__ W, const float* __restrict__ bvec,
               float* __restrict__ C) {
    __shared__ float As[128 * PITCH];
    __shared__ float Bs[64 * PITCH];

    const int tid  = threadIdx.x;
    const int bM   = blockIdx.x * 128;
    const int bN   = blockIdx.y * 64;
    const int lane = tid & 31;
    const int wid  = tid >> 5;
    const int wm   = wid & 3;
    const int wn   = wid >> 2;

    const int arow = tid >> 1;
    const int acol = (tid & 1) * 8;
    const int brow = tid & 63;
    const int bcol = (tid >> 6) * 4;
    const float* Ag = g_o + (size_t)(bM + arow) * CDIM + acol;
    const float* Wg = W   + (size_t)(bN + brow) * CDIM + bcol;

    float acc[2][4][4];
#pragma unroll
    for (int mt = 0; mt < 2; mt++)
#pragma unroll
        for (int nt = 0; nt < 4; nt++)
#pragma unroll
            for (int q = 0; q < 4; q++) acc[mt][nt][q] = 0.f;

    float4 pa0 = *(const float4*)(Ag);
    float4 pa1 = *(const float4*)(Ag + 4);
    float4 pb  = *(const float4*)(Wg);

    const int g4 = lane >> 2;
    const int t4 = lane & 3;

    for (int c = 0; c < 12; c++) {
        *(float4*)&As[arow * PITCH + acol]     = pa0;
        *(float4*)&As[arow * PITCH + acol + 4] = pa1;
        *(float4*)&Bs[brow * PITCH + bcol]     = pb;
        __syncthreads();

        if (c < 11) {
            pa0 = *(const float4*)(Ag + (c + 1) * 16);
            pa1 = *(const float4*)(Ag + (c + 1) * 16 + 4);
            pb  = *(const float4*)(Wg + (c + 1) * 16);
        }

#pragma unroll
        for (int ks = 0; ks < 16; ks += 8) {
            uint32_t Ab[2][4], Asm[2][4];
#pragma unroll
            for (int mt = 0; mt < 2; mt++) {
                const int r = wm * 32 + mt * 16 + g4;
#pragma unroll
                for (int q = 0; q < 4; q++) {
                    int rr = r + (q & 1) * 8;
                    int cc = ks + t4 + (q >> 1) * 4;
                    tf32_split(As[rr * PITCH + cc], Ab[mt][q], Asm[mt][q]);
                }
            }
            uint32_t Bb[4][2], Bsm[4][2];
#pragma unroll
            for (int nt = 0; nt < 4; nt++) {
                const int nb = wn * 32 + nt * 8 + g4;
#pragma unroll
                for (int q = 0; q < 2; q++) {
                    int cc = ks + t4 + q * 4;
                    tf32_split(Bs[nb * PITCH + cc], Bb[nt][q], Bsm[nt][q]);
                }
            }
#pragma unroll
            for (int mt = 0; mt < 2; mt++)
#pragma unroll
                for (int nt = 0; nt < 4; nt++) {
                    MMA_TF32(acc[mt][nt], Ab[mt], Bb[nt]);
                    MMA_TF32(acc[mt][nt], Ab[mt], Bsm[nt]);
                    MMA_TF32(acc[mt][nt], Asm[mt], Bb[nt]);
                }
        }
        __syncthreads();
    }

#pragma unroll
    for (int mt = 0; mt < 2; mt++) {
        int r0 = bM + wm * 32 + mt * 16 + g4;
        int r1 = r0 + 8;
#pragma unroll
        for (int nt = 0; nt < 4; nt++) {
            int c0 = bN + wn * 32 + nt * 8 + t4 * 2;
            float bb0 = bvec[c0], bb1 = bvec[c0 + 1];
            float2 v0, v1;
            v0.x = acc[mt][nt][0] + bb0;
            v0.y = acc[mt][nt][1] + bb1;
            v1.x = acc[mt][nt][2] + bb0;
            v1.y = acc[mt][nt][3] + bb1;
            *(float2*)&C[(size_t)r0 * CDIM + c0] = v0;
            *(float2*)&C[(size_t)r1 * CDIM + c0] = v1;
        }
    }
}

// ============================================================
extern "C" void kernel_launch(void* const* d_in, const int* in_sizes, int n_in,
                              void* d_out, int out_size) {
    const float* x      = (const float*)d_in[0];
    const float* mask   = (const float*)d_in[1];
    const float* qkv_w  = (const float*)d_in[2];
    const float* qkv_b  = (const float*)d_in[3];
    const float* proj_w = (const float*)d_in[4];
    const float* proj_b = (const float*)d_in[5];
    const float* rpb    = (const float*)d_in[6];
    const int*   rel    = (const int*)d_in[7];
    float* out = (float*)d_out;

    bias_gather<<<(NH * NTOK * NTOK + 255) / 256, 256>>>(rpb, rel);

    dim3 g1(ROWS / 128, QKVN / 64);     // 3136 x 9
    qkv_gemm<<<g1, 256>>>(x, qkv_w, qkv_b);

    attn_kernel<<<BTOT * NH, 128>>>(mask);

    dim3 g2(ROWS / 128, CDIM / 64);     // 3136 x 3
    proj_gemm<<<g2, 256>>>(proj_w, proj_b, out);
}

// round 8
// speedup vs baseline: 2.8756x; 1.3599x over previous
#include <cuda_runtime.h>
#include <cstdint>

#define NTOK 98
#define NN2  (NTOK*NTOK)          // 9604
#define CDIM 192
#define NH   6
#define HD   32
#define NWIN 64
#define BTOT 4096
#define ROWS (BTOT*NTOK)          // 401408
#define QKVN (3*CDIM)             // 576
#define PER_TENSOR (BTOT*NH*NTOK*HD)   // 77,070,336

// ---- scratch ----
__device__ float g_q[PER_TENSOR];
__device__ float g_k[PER_TENSOR];
__device__ float g_v[PER_TENSOR];
__device__ float g_o[ROWS*CDIM];             // attention output, (b, n, C) layout
__device__ float g_bm[NH*NWIN*NN2];          // combined bias+mask, (h, w, i, j)

// ---- tf32 helpers ----
__device__ __forceinline__ uint32_t f2tf(float x) {
    uint32_t r; asm("cvt.rna.tf32.f32 %0, %1;" : "=r"(r) : "f"(x)); return r;
}
__device__ __forceinline__ void tf32_split(float x, uint32_t& big, uint32_t& small) {
    big = f2tf(x);
    small = f2tf(x - __uint_as_float(big));
}

#define MMA_TF32(d, a, b)                                                     \
    asm volatile(                                                             \
        "mma.sync.aligned.m16n8k8.row.col.f32.tf32.tf32.f32 "                 \
        "{%0,%1,%2,%3}, {%4,%5,%6,%7}, {%8,%9}, {%0,%1,%2,%3};"               \
        : "+f"(d[0]), "+f"(d[1]), "+f"(d[2]), "+f"(d[3])                      \
        : "r"(a[0]), "r"(a[1]), "r"(a[2]), "r"(a[3]), "r"(b[0]), "r"(b[1]))

// ============================================================
// Kernel 1: combined bias+mask table: bm[h][w][i][j] = table[rel[ij]*NH+h] + mask[w][ij]
// ============================================================
__global__ void bm_prep(const float* __restrict__ table, const int* __restrict__ rel,
                        const float* __restrict__ mask) {
    int idx = blockIdx.x * 256 + threadIdx.x;
    if (idx < NH * NWIN * NN2) {
        int h   = idx / (NWIN * NN2);
        int rem = idx - h * (NWIN * NN2);
        int w   = rem / NN2;
        int ij  = rem - w * NN2;
        g_bm[idx] = table[rel[ij] * NH + h] + mask[w * NN2 + ij];
    }
}

// ============================================================
// Kernel 2: QKV GEMM via 3xTF32 mma (proven R6 version, unchanged).
// ============================================================
#define PITCH 20

__global__ __launch_bounds__(256)
void qkv_gemm(const float* __restrict__ A, const float* __restrict__ W,
              const float* __restrict__ bvec) {
    __shared__ float As[128 * PITCH];
    __shared__ float Bs[64 * PITCH];

    const int tid  = threadIdx.x;
    const int bM   = blockIdx.x * 128;
    const int bN   = blockIdx.y * 64;
    const int lane = tid & 31;
    const int wid  = tid >> 5;
    const int wm   = wid & 3;
    const int wn   = wid >> 2;

    const int arow = tid >> 1;
    const int acol = (tid & 1) * 8;
    const int brow = tid & 63;
    const int bcol = (tid >> 6) * 4;
    const float* Ag = A + (size_t)(bM + arow) * CDIM + acol;
    const float* Wg = W + (size_t)(bN + brow) * CDIM + bcol;

    float acc[2][4][4];
#pragma unroll
    for (int mt = 0; mt < 2; mt++)
#pragma unroll
        for (int nt = 0; nt < 4; nt++)
#pragma unroll
            for (int q = 0; q < 4; q++) acc[mt][nt][q] = 0.f;

    float4 pa0 = *(const float4*)(Ag);
    float4 pa1 = *(const float4*)(Ag + 4);
    float4 pb  = *(const float4*)(Wg);

    const int g4 = lane >> 2;
    const int t4 = lane & 3;

    for (int c = 0; c < 12; c++) {
        *(float4*)&As[arow * PITCH + acol]     = pa0;
        *(float4*)&As[arow * PITCH + acol + 4] = pa1;
        *(float4*)&Bs[brow * PITCH + bcol]     = pb;
        __syncthreads();

        if (c < 11) {
            pa0 = *(const float4*)(Ag + (c + 1) * 16);
            pa1 = *(const float4*)(Ag + (c + 1) * 16 + 4);
            pb  = *(const float4*)(Wg + (c + 1) * 16);
        }

#pragma unroll
        for (int ks = 0; ks < 16; ks += 8) {
            uint32_t Ab[2][4], Asm[2][4];
#pragma unroll
            for (int mt = 0; mt < 2; mt++) {
                const int r = wm * 32 + mt * 16 + g4;
#pragma unroll
                for (int q = 0; q < 4; q++) {
                    int rr = r + (q & 1) * 8;
                    int cc = ks + t4 + (q >> 1) * 4;
                    tf32_split(As[rr * PITCH + cc], Ab[mt][q], Asm[mt][q]);
                }
            }
            uint32_t Bb[4][2], Bsm[4][2];
#pragma unroll
            for (int nt = 0; nt < 4; nt++) {
                const int nb = wn * 32 + nt * 8 + g4;
#pragma unroll
                for (int q = 0; q < 2; q++) {
                    int cc = ks + t4 + q * 4;
                    tf32_split(Bs[nb * PITCH + cc], Bb[nt][q], Bsm[nt][q]);
                }
            }
#pragma unroll
            for (int mt = 0; mt < 2; mt++)
#pragma unroll
                for (int nt = 0; nt < 4; nt++) {
                    MMA_TF32(acc[mt][nt], Ab[mt], Bb[nt]);
                    MMA_TF32(acc[mt][nt], Ab[mt], Bsm[nt]);
                    MMA_TF32(acc[mt][nt], Asm[mt], Bb[nt]);
                }
        }
        __syncthreads();
    }

    const float scale = 0.17677669529663687f;
#pragma unroll
    for (int mt = 0; mt < 2; mt++) {
        int r0 = bM + wm * 32 + mt * 16 + g4;
        int r1 = r0 + 8;
        int b0 = r0 / NTOK, n0 = r0 - b0 * NTOK;
        int b1 = r1 / NTOK, n1 = r1 - b1 * NTOK;
#pragma unroll
        for (int nt = 0; nt < 4; nt++) {
            int c0  = bN + wn * 32 + nt * 8 + t4 * 2;
            int t   = c0 / CDIM;
            int rem = c0 - t * CDIM;
            int hh  = rem >> 5;
            int d   = rem & 31;
            float* tgt = (t == 0) ? g_q : (t == 1) ? g_k : g_v;
            float sc   = (t == 0) ? scale : 1.0f;
            float bb0 = bvec[c0], bb1 = bvec[c0 + 1];
            float2 v0, v1;
            v0.x = (acc[mt][nt][0] + bb0) * sc;
            v0.y = (acc[mt][nt][1] + bb1) * sc;
            v1.x = (acc[mt][nt][2] + bb0) * sc;
            v1.y = (acc[mt][nt][3] + bb1) * sc;
            size_t o0 = (((size_t)b0 * NH + hh) * NTOK + n0) * HD + d;
            size_t o1 = (((size_t)b1 * NH + hh) * NTOK + n1) * HD + d;
            *(float2*)&tgt[o0] = v0;
            *(float2*)&tgt[o1] = v1;
        }
    }
}

// ============================================================
// Kernel 3: tensor-core attention. One CTA per (b,h), 224 threads (7 warps).
// Warp w owns rows [16w, 16w+16). S = QK^T via 3xTF32 mma (13 n-tiles of 8,
// K padded to 104 with zeros). bias+mask from g_bm. Softmax in quads.
// PV: P shuffled accum->A-frag layout in-register, 3xTF32 again.
// ============================================================
#define SPITCH 40
#define NT13 13

__global__ __launch_bounds__(224)
void attn_tc(int dummy) {
    __shared__ float Qf[112 * SPITCH];
    __shared__ float Kf[104 * SPITCH];
    __shared__ float Vf[104 * SPITCH];

    const int bh = blockIdx.x;
    const int b  = bh / NH;
    const int h  = bh - b * NH;
    const int w  = b & (NWIN - 1);

    const float* Qp = g_q + (size_t)bh * NTOK * HD;
    const float* Kp = g_k + (size_t)bh * NTOK * HD;
    const float* Vp = g_v + (size_t)bh * NTOK * HD;

    const int tid = threadIdx.x;

    // zero pads (rows >=98, cols 32..39)
    for (int i = tid; i < 112 * SPITCH / 4; i += 224) *(float4*)&Qf[i * 4] = make_float4(0, 0, 0, 0);
    for (int i = tid; i < 104 * SPITCH / 4; i += 224) {
        *(float4*)&Kf[i * 4] = make_float4(0, 0, 0, 0);
        *(float4*)&Vf[i * 4] = make_float4(0, 0, 0, 0);
    }
    __syncthreads();

    for (int idx = tid; idx < NTOK * HD; idx += 224) {
        int r = idx >> 5, d = idx & 31;
        Qf[r * SPITCH + d] = Qp[idx];
        Kf[r * SPITCH + d] = Kp[idx];
        Vf[r * SPITCH + d] = Vp[idx];
    }
    __syncthreads();

    const int warp = tid >> 5;       // 0..6 = band
    const int lane = tid & 31;
    const int g4   = lane >> 2;
    const int t4   = lane & 3;

    // ---- QK^T ----
    uint32_t Ab[4][4], Asm[4][4];
#pragma unroll
    for (int kq = 0; kq < 4; kq++)
#pragma unroll
        for (int q = 0; q < 4; q++) {
            int r = warp * 16 + g4 + (q & 1) * 8;
            int c = kq * 8 + t4 + (q >> 1) * 4;
            tf32_split(Qf[r * SPITCH + c], Ab[kq][q], Asm[kq][q]);
        }

    float acc[NT13][4];
#pragma unroll
    for (int nt = 0; nt < NT13; nt++)
#pragma unroll
        for (int q = 0; q < 4; q++) acc[nt][q] = 0.f;

#pragma unroll
    for (int nt = 0; nt < NT13; nt++) {
#pragma unroll
        for (int kq = 0; kq < 4; kq++) {
            uint32_t Bb[2], Bs[2];
#pragma unroll
            for (int q = 0; q < 2; q++) {
                int j = nt * 8 + g4;
                int c = kq * 8 + t4 + q * 4;
                tf32_split(Kf[j * SPITCH + c], Bb[q], Bs[q]);
            }
            MMA_TF32(acc[nt], Ab[kq], Bb);
            MMA_TF32(acc[nt], Ab[kq], Bs);
            MMA_TF32(acc[nt], Asm[kq], Bb);
        }
    }

    // ---- add bias+mask, mask out padded columns ----
    const float* bmp = g_bm + (size_t)(h * NWIN + w) * NN2;
    const int r0 = warp * 16 + g4;
    const int r1 = r0 + 8;
#pragma unroll
    for (int nt = 0; nt < NT13; nt++) {
        int j = nt * 8 + t4 * 2;
        if (j < NTOK) {
            if (r0 < NTOK) {
                float2 m0 = *(const float2*)&bmp[r0 * NTOK + j];
                acc[nt][0] += m0.x; acc[nt][1] += m0.y;
            }
            if (r1 < NTOK) {
                float2 m1 = *(const float2*)&bmp[r1 * NTOK + j];
                acc[nt][2] += m1.x; acc[nt][3] += m1.y;
            }
        } else {
            acc[nt][0] = -1e30f; acc[nt][1] = -1e30f;
            acc[nt][2] = -1e30f; acc[nt][3] = -1e30f;
        }
    }

    // ---- softmax (rows r0 in slots 0/1, r1 in slots 2/3; reduce in quad) ----
    float mx0 = -1e30f, mx1 = -1e30f;
#pragma unroll
    for (int nt = 0; nt < NT13; nt++) {
        mx0 = fmaxf(mx0, fmaxf(acc[nt][0], acc[nt][1]));
        mx1 = fmaxf(mx1, fmaxf(acc[nt][2], acc[nt][3]));
    }
#pragma unroll
    for (int off = 1; off <= 2; off <<= 1) {
        mx0 = fmaxf(mx0, __shfl_xor_sync(0xffffffffu, mx0, off));
        mx1 = fmaxf(mx1, __shfl_xor_sync(0xffffffffu, mx1, off));
    }
    float s0 = 0.f, s1 = 0.f;
#pragma unroll
    for (int nt = 0; nt < NT13; nt++) {
        acc[nt][0] = __expf(acc[nt][0] - mx0);
        acc[nt][1] = __expf(acc[nt][1] - mx0);
        acc[nt][2] = __expf(acc[nt][2] - mx1);
        acc[nt][3] = __expf(acc[nt][3] - mx1);
        s0 += acc[nt][0] + acc[nt][1];
        s1 += acc[nt][2] + acc[nt][3];
    }
#pragma unroll
    for (int off = 1; off <= 2; off <<= 1) {
        s0 += __shfl_xor_sync(0xffffffffu, s0, off);
        s1 += __shfl_xor_sync(0xffffffffu, s1, off);
    }
    const float inv0 = 1.0f / s0, inv1 = 1.0f / s1;
#pragma unroll
    for (int nt = 0; nt < NT13; nt++) {
        acc[nt][0] *= inv0; acc[nt][1] *= inv0;
        acc[nt][2] *= inv1; acc[nt][3] *= inv1;
    }

    // ---- PV ----
    float out[4][4];
#pragma unroll
    for (int nt = 0; nt < 4; nt++)
#pragma unroll
        for (int q = 0; q < 4; q++) out[nt][q] = 0.f;

    const int basel = lane & ~3;
    const int l0 = basel + (t4 >> 1);
    const int l2 = l0 + 2;
    const bool hi = (t4 & 1);

#pragma unroll
    for (int kt = 0; kt < NT13; kt++) {
        float d0 = acc[kt][0], d1 = acc[kt][1], d2 = acc[kt][2], d3 = acc[kt][3];
        float p0a = __shfl_sync(0xffffffffu, d0, l0);
        float p0b = __shfl_sync(0xffffffffu, d1, l0);
        float p2a = __shfl_sync(0xffffffffu, d0, l2);
        float p2b = __shfl_sync(0xffffffffu, d1, l2);
        float p1a = __shfl_sync(0xffffffffu, d2, l0);
        float p1b = __shfl_sync(0xffffffffu, d3, l0);
        float p3a = __shfl_sync(0xffffffffu, d2, l2);
        float p3b = __shfl_sync(0xffffffffu, d3, l2);
        float a0 = hi ? p0b : p0a;     // P(g4,    kt*8+t4)
        float a1 = hi ? p1b : p1a;     // P(g4+8,  kt*8+t4)
        float a2 = hi ? p2b : p2a;     // P(g4,    kt*8+t4+4)
        float a3 = hi ? p3b : p3a;     // P(g4+8,  kt*8+t4+4)

        uint32_t Pb[4], Ps[4];
        tf32_split(a0, Pb[0], Ps[0]);
        tf32_split(a1, Pb[1], Ps[1]);
        tf32_split(a2, Pb[2], Ps[2]);
        tf32_split(a3, Pb[3], Ps[3]);

#pragma unroll
        for (int nt = 0; nt < 4; nt++) {
            uint32_t Vb[2], Vs[2];
#pragma unroll
            for (int q = 0; q < 2; q++) {
                int j = kt * 8 + t4 + q * 4;
                int d = nt * 8 + g4;
                tf32_split(Vf[j * SPITCH + d], Vb[q], Vs[q]);
            }
            MMA_TF32(out[nt], Pb, Vb);
            MMA_TF32(out[nt], Pb, Vs);
            MMA_TF32(out[nt], Ps, Vb);
        }
    }

    // ---- write (b, n, C) ----
#pragma unroll
    for (int nt = 0; nt < 4; nt++) {
        int d = nt * 8 + 2 * t4;
        if (r0 < NTOK)
            *(float2*)&g_o[((size_t)(b * NTOK + r0)) * CDIM + h * HD + d] =
                make_float2(out[nt][0], out[nt][1]);
        if (r1 < NTOK)
            *(float2*)&g_o[((size_t)(b * NTOK + r1)) * CDIM + h * HD + d] =
                make_float2(out[nt][2], out[nt][3]);
    }
}

// ============================================================
// Kernel 4: projection GEMM via 3xTF32 mma (proven R6 version, unchanged).
// ============================================================
__global__ __launch_bounds__(256)
void proj_gemm(const float* __restrict__ W, const float* __restrict__ bvec,
               float* __restrict__ C) {
    __shared__ float As[128 * PITCH];
    __shared__ float Bs[64 * PITCH];

    const int tid  = threadIdx.x;
    const int bM   = blockIdx.x * 128;
    const int bN   = blockIdx.y * 64;
    const int lane = tid & 31;
    const int wid  = tid >> 5;
    const int wm   = wid & 3;
    const int wn   = wid >> 2;

    const int arow = tid >> 1;
    const int acol = (tid & 1) * 8;
    const int brow = tid & 63;
    const int bcol = (tid >> 6) * 4;
    const float* Ag = g_o + (size_t)(bM + arow) * CDIM + acol;
    const float* Wg = W   + (size_t)(bN + brow) * CDIM + bcol;

    float acc[2][4][4];
#pragma unroll
    for (int mt = 0; mt < 2; mt++)
#pragma unroll
        for (int nt = 0; nt < 4; nt++)
#pragma unroll
            for (int q = 0; q < 4; q++) acc[mt][nt][q] = 0.f;

    float4 pa0 = *(const float4*)(Ag);
    float4 pa1 = *(const float4*)(Ag + 4);
    float4 pb  = *(const float4*)(Wg);

    const int g4 = lane >> 2;
    const int t4 = lane & 3;

    for (int c = 0; c < 12; c++) {
        *(float4*)&As[arow * PITCH + acol]     = pa0;
        *(float4*)&As[arow * PITCH + acol + 4] = pa1;
        *(float4*)&Bs[brow * PITCH + bcol]     = pb;
        __syncthreads();

        if (c < 11) {
            pa0 = *(const float4*)(Ag + (c + 1) * 16);
            pa1 = *(const float4*)(Ag + (c + 1) * 16 + 4);
            pb  = *(const float4*)(Wg + (c + 1) * 16);
        }

#pragma unroll
        for (int ks = 0; ks < 16; ks += 8) {
            uint32_t Ab[2][4], Asm[2][4];
#pragma unroll
            for (int mt = 0; mt < 2; mt++) {
                const int r = wm * 32 + mt * 16 + g4;
#pragma unroll
                for (int q = 0; q < 4; q++) {
                    int rr = r + (q & 1) * 8;
                    int cc = ks + t4 + (q >> 1) * 4;
                    tf32_split(As[rr * PITCH + cc], Ab[mt][q], Asm[mt][q]);
                }
            }
            uint32_t Bb[4][2], Bsm[4][2];
#pragma unroll
            for (int nt = 0; nt < 4; nt++) {
                const int nb = wn * 32 + nt * 8 + g4;
#pragma unroll
                for (int q = 0; q < 2; q++) {
                    int cc = ks + t4 + q * 4;
                    tf32_split(Bs[nb * PITCH + cc], Bb[nt][q], Bsm[nt][q]);
                }
            }
#pragma unroll
            for (int mt = 0; mt < 2; mt++)
#pragma unroll
                for (int nt = 0; nt < 4; nt++) {
                    MMA_TF32(acc[mt][nt], Ab[mt], Bb[nt]);
                    MMA_TF32(acc[mt][nt], Ab[mt], Bsm[nt]);
                    MMA_TF32(acc[mt][nt], Asm[mt], Bb[nt]);
                }
        }
        __syncthreads();
    }

#pragma unroll
    for (int mt = 0; mt < 2; mt++) {
        int r0 = bM + wm * 32 + mt * 16 + g4;
        int r1 = r0 + 8;
#pragma unroll
        for (int nt = 0; nt < 4; nt++) {
            int c0 = bN + wn * 32 + nt * 8 + t4 * 2;
            float bb0 = bvec[c0], bb1 = bvec[c0 + 1];
            float2 v0, v1;
            v0.x = acc[mt][nt][0] + bb0;
            v0.y = acc[mt][nt][1] + bb1;
            v1.x = acc[mt][nt][2] + bb0;
            v1.y = acc[mt][nt][3] + bb1;
            *(float2*)&C[(size_t)r0 * CDIM + c0] = v0;
            *(float2*)&C[(size_t)r1 * CDIM + c0] = v1;
        }
    }
}

// ============================================================
extern "C" void kernel_launch(void* const* d_in, const int* in_sizes, int n_in,
                              void* d_out, int out_size) {
    const float* x      = (const float*)d_in[0];
    const float* mask   = (const float*)d_in[1];
    const float* qkv_w  = (const float*)d_in[2];
    const float* qkv_b  = (const float*)d_in[3];
    const float* proj_w = (const float*)d_in[4];
    const float* proj_b = (const float*)d_in[5];
    const float* rpb    = (const float*)d_in[6];
    const int*   rel    = (const int*)d_in[7];
    float* out = (float*)d_out;

    bm_prep<<<(NH * NWIN * NN2 + 255) / 256, 256>>>(rpb, rel, mask);

    dim3 g1(ROWS / 128, QKVN / 64);     // 3136 x 9
    qkv_gemm<<<g1, 256>>>(x, qkv_w, qkv_b);

    attn_tc<<<BTOT * NH, 224>>>(0);

    dim3 g2(ROWS / 128, CDIM / 64);     // 3136 x 3
    proj_gemm<<<g2, 256>>>(proj_w, proj_b, out);
}